// round 15
// baseline (speedup 1.0000x reference)
#include <cuda_runtime.h>
#include <cuda_bf16.h>
#include <cuda_fp16.h>
#include <cstdint>
#include <math.h>

#define NN 100000
#define NE 1600000
#define SCAN_B 98    // ceil(NN/1024)

// ---------------- scratch (static device memory; zero-initialized at load) ----------------
__device__ int    g_deg[NN];      // zeroed at end of k_scatter for next replay
__device__ int    g_incl[NN];
__device__ int    g_bsum[SCAN_B];
__device__ int    g_off[NN + 1];
__device__ int    g_pos[NE];
__device__ int    g_srcs[NE];
__device__ __half g_h1[NN * 64];     // layer-1 features, fp16 (values only)
__device__ float  g_s1[NN * 8];
__device__ float  g_t1[NN * 8];
__device__ float  g_z [NN * 64];
__device__ __half g_h2[NN * 16];     // layer-2 features, fp16 (values only)
__device__ float  g_s2[NN];
__device__ float  g_t2[NN];

// edge dtype detection (int64 vs int32), computed per-thread from L1-cached words
__device__ __forceinline__ int detect64(const int* __restrict__ w) {
    int is64 = 1;
    #pragma unroll
    for (int k = 0; k < 8; k++)
        if (__ldg(&w[2 * k + 1]) != 0) is64 = 0;
    return is64;
}

// histogram + record each edge's slot within its dst segment (single atomic pass).
// g_deg enters this kernel zeroed (static init on first call, scatter-end-zero after).
__global__ void k_hist(const int* __restrict__ w) {
    int i = blockIdx.x * blockDim.x + threadIdx.x;
    if (i >= NE) return;
    int is64 = detect64(w);
    long long di = is64 ? 2LL * (NE + (long long)i) : (long long)(NE + i);
    g_pos[i] = atomicAdd(&g_deg[w[di]], 1);
}

__global__ void k_scanA() {
    __shared__ int sh[1024];
    int i = blockIdx.x * 1024 + threadIdx.x;
    int v = (i < NN) ? g_deg[i] : 0;
    sh[threadIdx.x] = v;
    __syncthreads();
    #pragma unroll
    for (int ofs = 1; ofs < 1024; ofs <<= 1) {
        int add = (threadIdx.x >= ofs) ? sh[threadIdx.x - ofs] : 0;
        __syncthreads();
        sh[threadIdx.x] += add;
        __syncthreads();
    }
    if (i < NN) g_incl[i] = sh[threadIdx.x];
    if (threadIdx.x == 1023) g_bsum[blockIdx.x] = sh[1023];
}

// fused: every block redundantly scans the 98 block sums, then writes its g_off slice.
__global__ void k_scanC() {
    __shared__ int sh[256];
    __shared__ int boff_s[256];
    int t = threadIdx.x;
    int v = (t < SCAN_B) ? g_bsum[t] : 0;
    sh[t] = v;
    __syncthreads();
    #pragma unroll
    for (int ofs = 1; ofs < 256; ofs <<= 1) {
        int add = (t >= ofs) ? sh[t - ofs] : 0;
        __syncthreads();
        sh[t] += add;
        __syncthreads();
    }
    boff_s[t] = sh[t] - v;    // exclusive prefix of block sums
    __syncthreads();

    int i = blockIdx.x * 256 + t;
    if (i < NN) g_off[i + 1] = g_incl[i] + boff_s[i >> 10];
    if (i == 0) g_off[0] = 0;
}

// pure gather+store, no atomics (slot precomputed in k_hist).
// Also re-zeroes g_deg (already consumed by scanA/scanC) for the next replay.
__global__ void k_scatter(const int* __restrict__ w) {
    int i = blockIdx.x * blockDim.x + threadIdx.x;
    if (i >= NE) return;
    int is64 = detect64(w);
    int s = w[is64 ? 2LL * i : (long long)i];
    int d = w[is64 ? 2LL * (NE + (long long)i) : (long long)(NE + i)];
    g_srcs[g_off[d] + g_pos[i]] = s;
    if (i < NN) g_deg[i] = 0;
}

// ---------------- GEMM1 on HMMA: h1 = x @ W1, bf16 3-term split, inline W conversion ----------------
#define MMA16816(d, a, b0r, b1r) \
    asm volatile("mma.sync.aligned.m16n8k16.row.col.f32.bf16.bf16.f32 " \
        "{%0,%1,%2,%3}, {%4,%5,%6,%7}, {%8,%9}, {%0,%1,%2,%3};" \
        : "+f"((d)[0]), "+f"((d)[1]), "+f"((d)[2]), "+f"((d)[3]) \
        : "r"((a)[0]), "r"((a)[1]), "r"((a)[2]), "r"((a)[3]), "r"(b0r), "r"(b1r))

__global__ __launch_bounds__(128) void k_gemm1(
    const float* __restrict__ x, const float* __restrict__ W1,
    const float* __restrict__ a1s, const float* __restrict__ a1d)
{
    // stride 20 u32 -> frag LDS banks (20*(l>>2)+c)&31 all distinct: conflict-free
    __shared__ uint32_t xh[128][20], xl[128][20], wh[64][20], wl[64][20];
    const int t = threadIdx.x;
    const int w = t >> 5, l = t & 31;
    const int gid = l >> 2;   // groupID (row/col within fragment)
    const int c   = l & 3;    // thread-in-group (k pair / col pair)
    const int rowblk = blockIdx.x * 128;

    float acc[2][8][4];
    #pragma unroll
    for (int mt = 0; mt < 2; mt++)
        #pragma unroll
        for (int nt = 0; nt < 8; nt++)
            #pragma unroll
            for (int q = 0; q < 4; q++) acc[mt][nt][q] = 0.f;

    for (int kc = 0; kc < 8; kc++) {
        // stage x chunk: 128 rows x 32 cols fp32 -> bf16 hi/lo packed pairs
        #pragma unroll
        for (int it = 0; it < 8; it++) {
            int f = (it << 7) + t;
            int row = f >> 3, c4 = f & 7;
            int grow = rowblk + row;
            float4 v = make_float4(0.f, 0.f, 0.f, 0.f);
            if (grow < NN) v = *(const float4*)&x[grow * 256 + (kc << 5) + (c4 << 2)];
            uint32_t uh0, uh1, ul0, ul1;
            asm("cvt.rn.bf16x2.f32 %0, %1, %2;" : "=r"(uh0) : "f"(v.y), "f"(v.x));
            asm("cvt.rn.bf16x2.f32 %0, %1, %2;" : "=r"(uh1) : "f"(v.w), "f"(v.z));
            float e0 = v.x - __uint_as_float(uh0 << 16);
            float e1 = v.y - __uint_as_float(uh0 & 0xffff0000u);
            float e2 = v.z - __uint_as_float(uh1 << 16);
            float e3 = v.w - __uint_as_float(uh1 & 0xffff0000u);
            asm("cvt.rn.bf16x2.f32 %0, %1, %2;" : "=r"(ul0) : "f"(e1), "f"(e0));
            asm("cvt.rn.bf16x2.f32 %0, %1, %2;" : "=r"(ul1) : "f"(e3), "f"(e2));
            xh[row][(c4 << 1)]     = uh0;
            xh[row][(c4 << 1) + 1] = uh1;
            xl[row][(c4 << 1)]     = ul0;
            xl[row][(c4 << 1) + 1] = ul1;
        }
        // stage W chunk: [64 n][16 kpairs], converting fp32 W1 -> bf16 hi/lo inline.
        // wh[n][idx] packs k-pair (kc*32+2idx, +1) for output column n.
        #pragma unroll
        for (int it = 0; it < 8; it++) {
            int f = (it << 7) + t;
            int n = f >> 4, idx = f & 15;
            float w0 = __ldg(&W1[((kc << 5) + (idx << 1)) * 64 + n]);
            float w1 = __ldg(&W1[((kc << 5) + (idx << 1) + 1) * 64 + n]);
            uint32_t uh, ul;
            asm("cvt.rn.bf16x2.f32 %0, %1, %2;" : "=r"(uh) : "f"(w1), "f"(w0));
            float e0 = w0 - __uint_as_float(uh << 16);
            float e1 = w1 - __uint_as_float(uh & 0xffff0000u);
            asm("cvt.rn.bf16x2.f32 %0, %1, %2;" : "=r"(ul) : "f"(e1), "f"(e0));
            wh[n][idx] = uh;
            wl[n][idx] = ul;
        }
        __syncthreads();

        #pragma unroll
        for (int ks = 0; ks < 2; ks++) {
            int kb = ks << 3;
            int r0 = (w << 5) + gid;
            uint32_t ah0[4] = { xh[r0][kb+c],    xh[r0+8][kb+c],    xh[r0][kb+c+4],    xh[r0+8][kb+c+4] };
            uint32_t ah1[4] = { xh[r0+16][kb+c], xh[r0+24][kb+c],   xh[r0+16][kb+c+4], xh[r0+24][kb+c+4] };
            uint32_t al0[4] = { xl[r0][kb+c],    xl[r0+8][kb+c],    xl[r0][kb+c+4],    xl[r0+8][kb+c+4] };
            uint32_t al1[4] = { xl[r0+16][kb+c], xl[r0+24][kb+c],   xl[r0+16][kb+c+4], xl[r0+24][kb+c+4] };
            #pragma unroll
            for (int nt = 0; nt < 8; nt++) {
                int n = (nt << 3) + gid;
                uint32_t bh0 = wh[n][kb+c], bh1 = wh[n][kb+c+4];
                uint32_t bl0 = wl[n][kb+c], bl1 = wl[n][kb+c+4];
                MMA16816(acc[0][nt], ah0, bh0, bh1);
                MMA16816(acc[1][nt], ah1, bh0, bh1);
                MMA16816(acc[0][nt], ah0, bl0, bl1);
                MMA16816(acc[1][nt], ah1, bl0, bl1);
                MMA16816(acc[0][nt], al0, bh0, bh1);
                MMA16816(acc[1][nt], al1, bh0, bh1);
            }
        }
        __syncthreads();
    }

    // ---- epilogue: store h1 (fp16) + s1/t1 (fp32) ----
    float as0[8], as1[8], ad0[8], ad1[8];
    #pragma unroll
    for (int nt = 0; nt < 8; nt++) {
        as0[nt] = __ldg(&a1s[(nt << 3) + (c << 1)]);
        as1[nt] = __ldg(&a1s[(nt << 3) + (c << 1) + 1]);
        ad0[nt] = __ldg(&a1d[(nt << 3) + (c << 1)]);
        ad1[nt] = __ldg(&a1d[(nt << 3) + (c << 1) + 1]);
    }
    #pragma unroll
    for (int mt = 0; mt < 2; mt++) {
        #pragma unroll
        for (int hf = 0; hf < 2; hf++) {
            int r = rowblk + (w << 5) + (mt << 4) + (hf << 3) + gid;
            bool ok = (r < NN);
            #pragma unroll
            for (int nt = 0; nt < 8; nt++) {
                float d0 = acc[mt][nt][(hf << 1)];
                float d1 = acc[mt][nt][(hf << 1) + 1];
                if (ok) {
                    uint32_t hp;   // lo = d0 (ch), hi = d1 (ch+1)
                    asm("cvt.rn.f16x2.f32 %0, %1, %2;" : "=r"(hp) : "f"(d1), "f"(d0));
                    *(uint32_t*)&g_h1[r * 64 + (nt << 3) + (c << 1)] = hp;
                }
                float sp = d0 * as0[nt] + d1 * as1[nt];
                float tp = d0 * ad0[nt] + d1 * ad1[nt];
                sp += __shfl_xor_sync(0xffffffffu, sp, 1);
                sp += __shfl_xor_sync(0xffffffffu, sp, 2);
                tp += __shfl_xor_sync(0xffffffffu, tp, 1);
                tp += __shfl_xor_sync(0xffffffffu, tp, 2);
                if (ok && c == 0) { g_s1[r * 8 + nt] = sp; g_t1[r * 8 + nt] = tp; }
            }
        }
    }
}

// ---------------- Layer-1 aggregation: warp per dst node, 4 edges per iteration ----------------
__global__ void k_agg1() {
    int n = (blockIdx.x * blockDim.x + threadIdx.x) >> 5;
    if (n >= NN) return;
    const int lane = threadIdx.x & 31;
    const int grp  = lane >> 3;       // which edge of the quad
    const int h    = lane & 7;        // head 0..7 (channels 8h..8h+7)

    const float tn = g_t1[n * 8 + h];
    const int j0 = g_off[n], j1 = g_off[n + 1];

    float d = 0.f;
    float A0 = 0.f, A1 = 0.f, A2 = 0.f, A3 = 0.f;
    float A4 = 0.f, A5 = 0.f, A6 = 0.f, A7 = 0.f;

    #pragma unroll 2
    for (int j = j0 + grp; j < j1; j += 4) {
        int src = __ldg(&g_srcs[j]);
        float e = __ldg(&g_s1[src * 8 + h]) + tn;
        e = e > 0.f ? e : 0.2f * e;
        float p = __expf(e);
        uint4 hv = __ldg((const uint4*)&g_h1[src * 64 + (h << 3)]);
        float2 f0 = __half22float2(*(const __half2*)&hv.x);
        float2 f1 = __half22float2(*(const __half2*)&hv.y);
        float2 f2 = __half22float2(*(const __half2*)&hv.z);
        float2 f3 = __half22float2(*(const __half2*)&hv.w);
        d  += p;
        A0 += p * f0.x; A1 += p * f0.y;
        A2 += p * f1.x; A3 += p * f1.y;
        A4 += p * f2.x; A5 += p * f2.y;
        A6 += p * f3.x; A7 += p * f3.y;
    }
    #pragma unroll
    for (int o = 8; o <= 16; o <<= 1) {
        d  += __shfl_xor_sync(0xffffffffu, d,  o);
        A0 += __shfl_xor_sync(0xffffffffu, A0, o);
        A1 += __shfl_xor_sync(0xffffffffu, A1, o);
        A2 += __shfl_xor_sync(0xffffffffu, A2, o);
        A3 += __shfl_xor_sync(0xffffffffu, A3, o);
        A4 += __shfl_xor_sync(0xffffffffu, A4, o);
        A5 += __shfl_xor_sync(0xffffffffu, A5, o);
        A6 += __shfl_xor_sync(0xffffffffu, A6, o);
        A7 += __shfl_xor_sync(0xffffffffu, A7, o);
    }

    if (grp == 0) {
        float inv = 1.f / (d + 1e-16f);
        float r0 = A0 * inv, r1 = A1 * inv, r2 = A2 * inv, r3 = A3 * inv;
        float r4 = A4 * inv, r5 = A5 * inv, r6 = A6 * inv, r7 = A7 * inv;
        float4 za, zb;
        za.x = r0 > 0.f ? r0 : expm1f(r0);   // elu
        za.y = r1 > 0.f ? r1 : expm1f(r1);
        za.z = r2 > 0.f ? r2 : expm1f(r2);
        za.w = r3 > 0.f ? r3 : expm1f(r3);
        zb.x = r4 > 0.f ? r4 : expm1f(r4);
        zb.y = r5 > 0.f ? r5 : expm1f(r5);
        zb.z = r6 > 0.f ? r6 : expm1f(r6);
        zb.w = r7 > 0.f ? r7 : expm1f(r7);
        float4* zp = (float4*)&g_z[n * 64 + (h << 3)];
        zp[0] = za;
        zp[1] = zb;
    }
}

// ---------------- GEMM2: h2 = z @ W2 (+ s2/t2 epilogue), h2 stored fp16 ----------------
__global__ __launch_bounds__(128) void k_gemm2(
    const float* __restrict__ W2, const float* __restrict__ a2s, const float* __restrict__ a2d)
{
    __shared__ float zs[128][65];
    __shared__ __align__(16) float w2s[1024];
    const int t = threadIdx.x;
    const int base = blockIdx.x * 128;

    #pragma unroll
    for (int r = 0; r < 64; r++) {
        int i = (r << 7) + t;
        int row = i >> 6, col = i & 63;
        int grow = base + row;
        zs[row][col] = (grow < NN) ? g_z[grow * 64 + col] : 0.f;
    }
    #pragma unroll
    for (int r = 0; r < 8; r++) w2s[(r << 7) + t] = W2[(r << 7) + t];
    __syncthreads();

    int row = base + t;
    if (row >= NN) return;

    float acc[16];
    #pragma unroll
    for (int cc = 0; cc < 16; cc++) acc[cc] = 0.f;

    #pragma unroll 8
    for (int k = 0; k < 64; k++) {
        float a = zs[t][k];
        const float4* wp = (const float4*)&w2s[k << 4];
        float4 w0 = wp[0], w1 = wp[1], w2 = wp[2], w3 = wp[3];
        acc[0]  += a * w0.x; acc[1]  += a * w0.y; acc[2]  += a * w0.z; acc[3]  += a * w0.w;
        acc[4]  += a * w1.x; acc[5]  += a * w1.y; acc[6]  += a * w1.z; acc[7]  += a * w1.w;
        acc[8]  += a * w2.x; acc[9]  += a * w2.y; acc[10] += a * w2.z; acc[11] += a * w2.w;
        acc[12] += a * w3.x; acc[13] += a * w3.y; acc[14] += a * w3.z; acc[15] += a * w3.w;
    }

    float s = 0.f, tt = 0.f;
    #pragma unroll
    for (int cc = 0; cc < 16; cc++) { s += acc[cc] * a2s[cc]; tt += acc[cc] * a2d[cc]; }
    g_s2[row] = s;
    g_t2[row] = tt;

    uint32_t hp[8];
    #pragma unroll
    for (int cc = 0; cc < 8; cc++)
        asm("cvt.rn.f16x2.f32 %0, %1, %2;" : "=r"(hp[cc]) : "f"(acc[2*cc+1]), "f"(acc[2*cc]));
    uint4* op = (uint4*)&g_h2[row * 16];
    op[0] = make_uint4(hp[0], hp[1], hp[2], hp[3]);
    op[1] = make_uint4(hp[4], hp[5], hp[6], hp[7]);
}

// ---------------- Layer-2 aggregation + log_softmax fused, 4 edges per iteration ----------------
__global__ void k_agg2(float* __restrict__ out) {
    int n = (blockIdx.x * blockDim.x + threadIdx.x) >> 5;
    if (n >= NN) return;
    const int lane = threadIdx.x & 31;
    const int grp  = lane >> 3;
    const int g    = lane & 7;        // class pair (2g, 2g+1)

    const float tn = g_t2[n];
    const int j0 = g_off[n], j1 = g_off[n + 1];

    float d = 0.f, A0 = 0.f, A1 = 0.f;
    #pragma unroll 2
    for (int j = j0 + grp; j < j1; j += 4) {
        int src = __ldg(&g_srcs[j]);
        float e = __ldg(&g_s2[src]) + tn;
        e = e > 0.f ? e : 0.2f * e;
        float p = __expf(e);
        __half2 hv = __ldg((const __half2*)&g_h2[src * 16 + (g << 1)]);
        float2 f = __half22float2(hv);
        d  += p;
        A0 += p * f.x;
        A1 += p * f.y;
    }
    #pragma unroll
    for (int o = 8; o <= 16; o <<= 1) {
        d  += __shfl_xor_sync(0xffffffffu, d,  o);
        A0 += __shfl_xor_sync(0xffffffffu, A0, o);
        A1 += __shfl_xor_sync(0xffffffffu, A1, o);
    }

    float inv = 1.f / (d + 1e-16f);
    float l0 = A0 * inv, l1 = A1 * inv;

    float mx = fmaxf(l0, l1);
    #pragma unroll
    for (int o = 1; o <= 4; o <<= 1) mx = fmaxf(mx, __shfl_xor_sync(0xffffffffu, mx, o));
    float sm = expf(l0 - mx) + expf(l1 - mx);
    #pragma unroll
    for (int o = 1; o <= 4; o <<= 1) sm += __shfl_xor_sync(0xffffffffu, sm, o);
    float lg = logf(sm);
    if (grp == 0)
        *(float2*)&out[n * 16 + (g << 1)] = make_float2(l0 - mx - lg, l1 - mx - lg);
}

// ---------------- launch: CSR build on side stream overlapped with GEMM1 ----------------
static cudaStream_t g_side = 0;
static cudaEvent_t  g_evFork = 0, g_evJoin = 0;
static int g_res_ok = -1;

extern "C" void kernel_launch(void* const* d_in, const int* in_sizes, int n_in,
                              void* d_out, int out_size) {
    const float* x   = (const float*)d_in[0];
    const int*   ei  = (const int*)  d_in[1];
    const float* W1  = (const float*)d_in[2];
    const float* a1s = (const float*)d_in[3];
    const float* a1d = (const float*)d_in[4];
    const float* W2  = (const float*)d_in[5];
    const float* a2s = (const float*)d_in[6];
    const float* a2d = (const float*)d_in[7];
    float* out = (float*)d_out;

    if (g_res_ok < 0) {   // one-time resource creation (first call is uncaptured)
        cudaError_t e1 = cudaStreamCreateWithFlags(&g_side, cudaStreamNonBlocking);
        cudaError_t e2 = cudaEventCreateWithFlags(&g_evFork, cudaEventDisableTiming);
        cudaError_t e3 = cudaEventCreateWithFlags(&g_evJoin, cudaEventDisableTiming);
        g_res_ok = (e1 == cudaSuccess && e2 == cudaSuccess && e3 == cudaSuccess) ? 1 : 0;
    }
    cudaStream_t cs = (g_res_ok == 1) ? g_side : 0;

    if (g_res_ok == 1) {
        cudaEventRecord(g_evFork, 0);
        cudaStreamWaitEvent(g_side, g_evFork, 0);
    }

    // CSR build chain (independent of GEMM1): 4 kernels
    k_hist    <<<(NE + 255) / 256, 256, 0, cs>>>(ei);
    k_scanA   <<<SCAN_B, 1024, 0, cs>>>();
    k_scanC   <<<(NN + 255) / 256, 256, 0, cs>>>();
    k_scatter <<<(NE + 255) / 256, 256, 0, cs>>>(ei);

    // GEMM1 (HMMA, W split inline) on the capture stream, concurrent with CSR build
    k_gemm1   <<<(NN + 127) / 128, 128>>>(x, W1, a1s, a1d);

    if (g_res_ok == 1) {
        cudaEventRecord(g_evJoin, g_side);
        cudaStreamWaitEvent(0, g_evJoin, 0);
    }

    k_agg1  <<<(NN * 32 + 255) / 256, 256>>>();
    k_gemm2 <<<(NN + 127) / 128, 128>>>(W2, a2s, a2d);
    k_agg2  <<<(NN * 32 + 255) / 256, 256>>>(out);
}

// round 16
// speedup vs baseline: 1.0859x; 1.0859x over previous
#include <cuda_runtime.h>
#include <cuda_bf16.h>
#include <cuda_fp16.h>
#include <cstdint>
#include <math.h>

#define NN 100000
#define NE 1600000
#define SCAN_B 98    // ceil(NN/1024)
#define NSPLIT 50048 // chunk boundary (multiple of 128)

// ---------------- scratch (static device memory; no allocations) ----------------
__device__ int    g_is64;
__device__ int    g_deg[NN];      // zero-init at load; re-zeroed at end of k_scatter
__device__ int    g_incl[NN];
__device__ int    g_bsum[SCAN_B];
__device__ int    g_off[NN + 1];
__device__ int    g_pos[NE];
__device__ int    g_srcs[NE];
__device__ __half g_h1[NN * 64];     // layer-1 features, fp16 (values only)
__device__ float  g_s1[NN * 8];
__device__ float  g_t1[NN * 8];
__device__ float  g_z [NN * 64];
__device__ __half g_h2[NN * 16];     // layer-2 features, fp16 (values only)
__device__ float  g_s2[NN];
__device__ float  g_t2[NN];
__device__ __nv_bfloat16 g_w1h[256 * 64];   // W1 split, [n][k] n-major
__device__ __nv_bfloat16 g_w1l[256 * 64];

// ---------------- init: detect edge dtype only (1 warp; g_deg zeroed by scatter) ----------------
__global__ void k_init(const int* __restrict__ w) {
    if (threadIdx.x == 0) {
        int is64 = 1;
        #pragma unroll
        for (int k = 0; k < 8; k++)
            if (w[2 * k + 1] != 0) is64 = 0;
        g_is64 = is64;
    }
}

// histogram + record each edge's slot within its dst segment (single atomic pass)
__global__ void k_hist(const int* __restrict__ w) {
    int i = blockIdx.x * blockDim.x + threadIdx.x;
    if (i >= NE) return;
    long long di = g_is64 ? 2LL * (NE + (long long)i) : (long long)(NE + i);
    g_pos[i] = atomicAdd(&g_deg[w[di]], 1);
}

__global__ void k_scanA() {
    __shared__ int sh[1024];
    int i = blockIdx.x * 1024 + threadIdx.x;
    int v = (i < NN) ? g_deg[i] : 0;
    sh[threadIdx.x] = v;
    __syncthreads();
    #pragma unroll
    for (int ofs = 1; ofs < 1024; ofs <<= 1) {
        int add = (threadIdx.x >= ofs) ? sh[threadIdx.x - ofs] : 0;
        __syncthreads();
        sh[threadIdx.x] += add;
        __syncthreads();
    }
    if (i < NN) g_incl[i] = sh[threadIdx.x];
    if (threadIdx.x == 1023) g_bsum[blockIdx.x] = sh[1023];
}

// fused: every block redundantly scans the 98 block sums, then writes its g_off slice.
__global__ void k_scanC() {
    __shared__ int sh[256];
    __shared__ int boff_s[256];
    int t = threadIdx.x;
    int v = (t < SCAN_B) ? g_bsum[t] : 0;
    sh[t] = v;
    __syncthreads();
    #pragma unroll
    for (int ofs = 1; ofs < 256; ofs <<= 1) {
        int add = (t >= ofs) ? sh[t - ofs] : 0;
        __syncthreads();
        sh[t] += add;
        __syncthreads();
    }
    boff_s[t] = sh[t] - v;    // exclusive prefix of block sums
    __syncthreads();

    int i = blockIdx.x * 256 + t;
    if (i < NN) g_off[i + 1] = g_incl[i] + boff_s[i >> 10];
    if (i == 0) g_off[0] = 0;
}

// pure gather+store, no atomics (slot precomputed in k_hist).
// Re-zeroes g_deg (already consumed by scanA/scanC) for the next graph replay.
__global__ void k_scatter(const int* __restrict__ w) {
    int i = blockIdx.x * blockDim.x + threadIdx.x;
    if (i >= NE) return;
    int is64 = g_is64;
    int s = w[is64 ? 2LL * i : (long long)i];
    int d = w[is64 ? 2LL * (NE + (long long)i) : (long long)(NE + i)];
    g_srcs[g_off[d] + g_pos[i]] = s;
    if (i < NN) g_deg[i] = 0;
}

// ---------------- W1 bf16 hi/lo split (once per call, tiny) ----------------
__global__ void k_prepW(const float* __restrict__ W1) {
    int i = blockIdx.x * blockDim.x + threadIdx.x;
    if (i >= 256 * 64) return;
    int k = i >> 6, n = i & 63;
    float v = W1[i];
    __nv_bfloat16 h = __float2bfloat16(v);
    __nv_bfloat16 l = __float2bfloat16(v - __bfloat162float(h));
    g_w1h[n * 256 + k] = h;
    g_w1l[n * 256 + k] = l;
}

// ---------------- GEMM1 on HMMA: h1 = x @ W1, bf16 3-term split ----------------
#define MMA16816(d, a, b0r, b1r) \
    asm volatile("mma.sync.aligned.m16n8k16.row.col.f32.bf16.bf16.f32 " \
        "{%0,%1,%2,%3}, {%4,%5,%6,%7}, {%8,%9}, {%0,%1,%2,%3};" \
        : "+f"((d)[0]), "+f"((d)[1]), "+f"((d)[2]), "+f"((d)[3]) \
        : "r"((a)[0]), "r"((a)[1]), "r"((a)[2]), "r"((a)[3]), "r"(b0r), "r"(b1r))

__global__ __launch_bounds__(128) void k_gemm1(
    const float* __restrict__ x,
    const float* __restrict__ a1s, const float* __restrict__ a1d)
{
    // stride 20 u32 -> frag LDS banks (20*(l>>2)+c)&31 all distinct: conflict-free
    __shared__ uint32_t xh[128][20], xl[128][20], wh[64][20], wl[64][20];
    const int t = threadIdx.x;
    const int w = t >> 5, l = t & 31;
    const int gid = l >> 2;   // groupID (row/col within fragment)
    const int c   = l & 3;    // thread-in-group (k pair / col pair)
    const int rowblk = blockIdx.x * 128;

    float acc[2][8][4];
    #pragma unroll
    for (int mt = 0; mt < 2; mt++)
        #pragma unroll
        for (int nt = 0; nt < 8; nt++)
            #pragma unroll
            for (int q = 0; q < 4; q++) acc[mt][nt][q] = 0.f;

    const uint32_t* wph = (const uint32_t*)g_w1h;
    const uint32_t* wpl = (const uint32_t*)g_w1l;

    for (int kc = 0; kc < 8; kc++) {
        // stage x chunk: 128 rows x 32 cols fp32 -> bf16 hi/lo packed pairs
        #pragma unroll
        for (int it = 0; it < 8; it++) {
            int f = (it << 7) + t;
            int row = f >> 3, c4 = f & 7;
            int grow = rowblk + row;
            float4 v = make_float4(0.f, 0.f, 0.f, 0.f);
            if (grow < NN) v = *(const float4*)&x[grow * 256 + (kc << 5) + (c4 << 2)];
            uint32_t uh0, uh1, ul0, ul1;
            asm("cvt.rn.bf16x2.f32 %0, %1, %2;" : "=r"(uh0) : "f"(v.y), "f"(v.x));
            asm("cvt.rn.bf16x2.f32 %0, %1, %2;" : "=r"(uh1) : "f"(v.w), "f"(v.z));
            float e0 = v.x - __uint_as_float(uh0 << 16);
            float e1 = v.y - __uint_as_float(uh0 & 0xffff0000u);
            float e2 = v.z - __uint_as_float(uh1 << 16);
            float e3 = v.w - __uint_as_float(uh1 & 0xffff0000u);
            asm("cvt.rn.bf16x2.f32 %0, %1, %2;" : "=r"(ul0) : "f"(e1), "f"(e0));
            asm("cvt.rn.bf16x2.f32 %0, %1, %2;" : "=r"(ul1) : "f"(e3), "f"(e2));
            xh[row][(c4 << 1)]     = uh0;
            xh[row][(c4 << 1) + 1] = uh1;
            xl[row][(c4 << 1)]     = ul0;
            xl[row][(c4 << 1) + 1] = ul1;
        }
        // stage W chunk: [64 n][16 kpairs] = 1024 entries -> 8 iterations of 128 threads
        #pragma unroll
        for (int it = 0; it < 8; it++) {
            int f = (it << 7) + t;
            int n = f >> 4, idx = f & 15;
            wh[n][idx] = wph[n * 128 + (kc << 4) + idx];
            wl[n][idx] = wpl[n * 128 + (kc << 4) + idx];
        }
        __syncthreads();

        #pragma unroll
        for (int ks = 0; ks < 2; ks++) {
            int kb = ks << 3;
            int r0 = (w << 5) + gid;
            uint32_t ah0[4] = { xh[r0][kb+c],    xh[r0+8][kb+c],    xh[r0][kb+c+4],    xh[r0+8][kb+c+4] };
            uint32_t ah1[4] = { xh[r0+16][kb+c], xh[r0+24][kb+c],   xh[r0+16][kb+c+4], xh[r0+24][kb+c+4] };
            uint32_t al0[4] = { xl[r0][kb+c],    xl[r0+8][kb+c],    xl[r0][kb+c+4],    xl[r0+8][kb+c+4] };
            uint32_t al1[4] = { xl[r0+16][kb+c], xl[r0+24][kb+c],   xl[r0+16][kb+c+4], xl[r0+24][kb+c+4] };
            #pragma unroll
            for (int nt = 0; nt < 8; nt++) {
                int n = (nt << 3) + gid;
                uint32_t bh0 = wh[n][kb+c], bh1 = wh[n][kb+c+4];
                uint32_t bl0 = wl[n][kb+c], bl1 = wl[n][kb+c+4];
                MMA16816(acc[0][nt], ah0, bh0, bh1);
                MMA16816(acc[1][nt], ah1, bh0, bh1);
                MMA16816(acc[0][nt], ah0, bl0, bl1);
                MMA16816(acc[1][nt], ah1, bl0, bl1);
                MMA16816(acc[0][nt], al0, bh0, bh1);
                MMA16816(acc[1][nt], al1, bh0, bh1);
            }
        }
        __syncthreads();
    }

    // ---- epilogue: store h1 (fp16) + s1/t1 (fp32) ----
    float as0[8], as1[8], ad0[8], ad1[8];
    #pragma unroll
    for (int nt = 0; nt < 8; nt++) {
        as0[nt] = __ldg(&a1s[(nt << 3) + (c << 1)]);
        as1[nt] = __ldg(&a1s[(nt << 3) + (c << 1) + 1]);
        ad0[nt] = __ldg(&a1d[(nt << 3) + (c << 1)]);
        ad1[nt] = __ldg(&a1d[(nt << 3) + (c << 1) + 1]);
    }
    #pragma unroll
    for (int mt = 0; mt < 2; mt++) {
        #pragma unroll
        for (int hf = 0; hf < 2; hf++) {
            int r = rowblk + (w << 5) + (mt << 4) + (hf << 3) + gid;
            bool ok = (r < NN);
            #pragma unroll
            for (int nt = 0; nt < 8; nt++) {
                float d0 = acc[mt][nt][(hf << 1)];
                float d1 = acc[mt][nt][(hf << 1) + 1];
                if (ok) {
                    uint32_t hp;   // lo = d0 (ch), hi = d1 (ch+1)
                    asm("cvt.rn.f16x2.f32 %0, %1, %2;" : "=r"(hp) : "f"(d1), "f"(d0));
                    *(uint32_t*)&g_h1[r * 64 + (nt << 3) + (c << 1)] = hp;
                }
                float sp = d0 * as0[nt] + d1 * as1[nt];
                float tp = d0 * ad0[nt] + d1 * ad1[nt];
                sp += __shfl_xor_sync(0xffffffffu, sp, 1);
                sp += __shfl_xor_sync(0xffffffffu, sp, 2);
                tp += __shfl_xor_sync(0xffffffffu, tp, 1);
                tp += __shfl_xor_sync(0xffffffffu, tp, 2);
                if (ok && c == 0) { g_s1[r * 8 + nt] = sp; g_t1[r * 8 + nt] = tp; }
            }
        }
    }
}

// ---------------- Layer-1 aggregation: warp per dst node, 4 edges per iteration ----------------
__global__ void k_agg1(int n0, int n1) {
    int n = n0 + ((blockIdx.x * blockDim.x + threadIdx.x) >> 5);
    if (n >= n1) return;
    const int lane = threadIdx.x & 31;
    const int grp  = lane >> 3;       // which edge of the quad
    const int h    = lane & 7;        // head 0..7 (channels 8h..8h+7)

    const float tn = g_t1[n * 8 + h];
    const int j0 = g_off[n], j1 = g_off[n + 1];

    float d = 0.f;
    float A0 = 0.f, A1 = 0.f, A2 = 0.f, A3 = 0.f;
    float A4 = 0.f, A5 = 0.f, A6 = 0.f, A7 = 0.f;

    #pragma unroll 2
    for (int j = j0 + grp; j < j1; j += 4) {
        int src = __ldg(&g_srcs[j]);
        float e = __ldg(&g_s1[src * 8 + h]) + tn;
        e = e > 0.f ? e : 0.2f * e;
        float p = __expf(e);
        uint4 hv = __ldg((const uint4*)&g_h1[src * 64 + (h << 3)]);
        float2 f0 = __half22float2(*(const __half2*)&hv.x);
        float2 f1 = __half22float2(*(const __half2*)&hv.y);
        float2 f2 = __half22float2(*(const __half2*)&hv.z);
        float2 f3 = __half22float2(*(const __half2*)&hv.w);
        d  += p;
        A0 += p * f0.x; A1 += p * f0.y;
        A2 += p * f1.x; A3 += p * f1.y;
        A4 += p * f2.x; A5 += p * f2.y;
        A6 += p * f3.x; A7 += p * f3.y;
    }
    #pragma unroll
    for (int o = 8; o <= 16; o <<= 1) {
        d  += __shfl_xor_sync(0xffffffffu, d,  o);
        A0 += __shfl_xor_sync(0xffffffffu, A0, o);
        A1 += __shfl_xor_sync(0xffffffffu, A1, o);
        A2 += __shfl_xor_sync(0xffffffffu, A2, o);
        A3 += __shfl_xor_sync(0xffffffffu, A3, o);
        A4 += __shfl_xor_sync(0xffffffffu, A4, o);
        A5 += __shfl_xor_sync(0xffffffffu, A5, o);
        A6 += __shfl_xor_sync(0xffffffffu, A6, o);
        A7 += __shfl_xor_sync(0xffffffffu, A7, o);
    }

    if (grp == 0) {
        float inv = 1.f / (d + 1e-16f);
        float r0 = A0 * inv, r1 = A1 * inv, r2 = A2 * inv, r3 = A3 * inv;
        float r4 = A4 * inv, r5 = A5 * inv, r6 = A6 * inv, r7 = A7 * inv;
        float4 za, zb;
        za.x = r0 > 0.f ? r0 : expm1f(r0);   // elu
        za.y = r1 > 0.f ? r1 : expm1f(r1);
        za.z = r2 > 0.f ? r2 : expm1f(r2);
        za.w = r3 > 0.f ? r3 : expm1f(r3);
        zb.x = r4 > 0.f ? r4 : expm1f(r4);
        zb.y = r5 > 0.f ? r5 : expm1f(r5);
        zb.z = r6 > 0.f ? r6 : expm1f(r6);
        zb.w = r7 > 0.f ? r7 : expm1f(r7);
        float4* zp = (float4*)&g_z[n * 64 + (h << 3)];
        zp[0] = za;
        zp[1] = zb;
    }
}

// ---------------- GEMM2: h2 = z @ W2 (+ s2/t2 epilogue), h2 stored fp16 ----------------
__global__ __launch_bounds__(128) void k_gemm2(
    const float* __restrict__ W2, const float* __restrict__ a2s, const float* __restrict__ a2d,
    int row0)
{
    __shared__ float zs[128][65];
    __shared__ __align__(16) float w2s[1024];
    const int t = threadIdx.x;
    const int base = row0 + blockIdx.x * 128;

    #pragma unroll
    for (int r = 0; r < 64; r++) {
        int i = (r << 7) + t;
        int row = i >> 6, col = i & 63;
        int grow = base + row;
        zs[row][col] = (grow < NN) ? g_z[grow * 64 + col] : 0.f;
    }
    #pragma unroll
    for (int r = 0; r < 8; r++) w2s[(r << 7) + t] = W2[(r << 7) + t];
    __syncthreads();

    int row = base + t;
    if (row >= NN) return;

    float acc[16];
    #pragma unroll
    for (int cc = 0; cc < 16; cc++) acc[cc] = 0.f;

    #pragma unroll 8
    for (int k = 0; k < 64; k++) {
        float a = zs[t][k];
        const float4* wp = (const float4*)&w2s[k << 4];
        float4 w0 = wp[0], w1 = wp[1], w2 = wp[2], w3 = wp[3];
        acc[0]  += a * w0.x; acc[1]  += a * w0.y; acc[2]  += a * w0.z; acc[3]  += a * w0.w;
        acc[4]  += a * w1.x; acc[5]  += a * w1.y; acc[6]  += a * w1.z; acc[7]  += a * w1.w;
        acc[8]  += a * w2.x; acc[9]  += a * w2.y; acc[10] += a * w2.z; acc[11] += a * w2.w;
        acc[12] += a * w3.x; acc[13] += a * w3.y; acc[14] += a * w3.z; acc[15] += a * w3.w;
    }

    float s = 0.f, tt = 0.f;
    #pragma unroll
    for (int cc = 0; cc < 16; cc++) { s += acc[cc] * a2s[cc]; tt += acc[cc] * a2d[cc]; }
    g_s2[row] = s;
    g_t2[row] = tt;

    uint32_t hp[8];
    #pragma unroll
    for (int cc = 0; cc < 8; cc++)
        asm("cvt.rn.f16x2.f32 %0, %1, %2;" : "=r"(hp[cc]) : "f"(acc[2*cc+1]), "f"(acc[2*cc]));
    uint4* op = (uint4*)&g_h2[row * 16];
    op[0] = make_uint4(hp[0], hp[1], hp[2], hp[3]);
    op[1] = make_uint4(hp[4], hp[5], hp[6], hp[7]);
}

// ---------------- Layer-2 aggregation + log_softmax fused, 4 edges per iteration ----------------
__global__ void k_agg2(float* __restrict__ out) {
    int n = (blockIdx.x * blockDim.x + threadIdx.x) >> 5;
    if (n >= NN) return;
    const int lane = threadIdx.x & 31;
    const int grp  = lane >> 3;
    const int g    = lane & 7;        // class pair (2g, 2g+1)

    const float tn = g_t2[n];
    const int j0 = g_off[n], j1 = g_off[n + 1];

    float d = 0.f, A0 = 0.f, A1 = 0.f;
    #pragma unroll 2
    for (int j = j0 + grp; j < j1; j += 4) {
        int src = __ldg(&g_srcs[j]);
        float e = __ldg(&g_s2[src]) + tn;
        e = e > 0.f ? e : 0.2f * e;
        float p = __expf(e);
        __half2 hv = __ldg((const __half2*)&g_h2[src * 16 + (g << 1)]);
        float2 f = __half22float2(hv);
        d  += p;
        A0 += p * f.x;
        A1 += p * f.y;
    }
    #pragma unroll
    for (int o = 8; o <= 16; o <<= 1) {
        d  += __shfl_xor_sync(0xffffffffu, d,  o);
        A0 += __shfl_xor_sync(0xffffffffu, A0, o);
        A1 += __shfl_xor_sync(0xffffffffu, A1, o);
    }

    float inv = 1.f / (d + 1e-16f);
    float l0 = A0 * inv, l1 = A1 * inv;

    float mx = fmaxf(l0, l1);
    #pragma unroll
    for (int o = 1; o <= 4; o <<= 1) mx = fmaxf(mx, __shfl_xor_sync(0xffffffffu, mx, o));
    float sm = expf(l0 - mx) + expf(l1 - mx);
    #pragma unroll
    for (int o = 1; o <= 4; o <<= 1) sm += __shfl_xor_sync(0xffffffffu, sm, o);
    float lg = logf(sm);
    if (grp == 0)
        *(float2*)&out[n * 16 + (g << 1)] = make_float2(l0 - mx - lg, l1 - mx - lg);
}

// ---------------- launch: CSR || GEMM1 fork, then chunked agg1/gemm2 overlap ----------------
static cudaStream_t g_side = 0;
static cudaEvent_t  g_evFork = 0, g_evJoin = 0, g_evA = 0, g_evB = 0;
static int g_res_ok = -1;

extern "C" void kernel_launch(void* const* d_in, const int* in_sizes, int n_in,
                              void* d_out, int out_size) {
    const float* x   = (const float*)d_in[0];
    const int*   ei  = (const int*)  d_in[1];
    const float* W1  = (const float*)d_in[2];
    const float* a1s = (const float*)d_in[3];
    const float* a1d = (const float*)d_in[4];
    const float* W2  = (const float*)d_in[5];
    const float* a2s = (const float*)d_in[6];
    const float* a2d = (const float*)d_in[7];
    float* out = (float*)d_out;

    if (g_res_ok < 0) {   // one-time resource creation (first call is uncaptured)
        cudaError_t e1 = cudaStreamCreateWithFlags(&g_side, cudaStreamNonBlocking);
        cudaError_t e2 = cudaEventCreateWithFlags(&g_evFork, cudaEventDisableTiming);
        cudaError_t e3 = cudaEventCreateWithFlags(&g_evJoin, cudaEventDisableTiming);
        cudaError_t e4 = cudaEventCreateWithFlags(&g_evA, cudaEventDisableTiming);
        cudaError_t e5 = cudaEventCreateWithFlags(&g_evB, cudaEventDisableTiming);
        g_res_ok = (e1 == cudaSuccess && e2 == cudaSuccess && e3 == cudaSuccess &&
                    e4 == cudaSuccess && e5 == cudaSuccess) ? 1 : 0;
    }
    cudaStream_t cs = (g_res_ok == 1) ? g_side : 0;

    if (g_res_ok == 1) {
        cudaEventRecord(g_evFork, 0);
        cudaStreamWaitEvent(g_side, g_evFork, 0);
    }

    // CSR build chain (independent of GEMM1); k_init is 1 warp (detect only)
    k_init    <<<1, 32, 0, cs>>>(ei);
    k_hist    <<<(NE + 255) / 256, 256, 0, cs>>>(ei);
    k_scanA   <<<SCAN_B, 1024, 0, cs>>>();
    k_scanC   <<<(NN + 255) / 256, 256, 0, cs>>>();
    k_scatter <<<(NE + 255) / 256, 256, 0, cs>>>(ei);

    // W split + GEMM1 (HMMA) on the capture stream, concurrent with CSR build
    k_prepW   <<<(256 * 64 + 255) / 256, 256>>>(W1);
    k_gemm1   <<<(NN + 127) / 128, 128>>>(x, a1s, a1d);

    if (g_res_ok == 1) {
        cudaEventRecord(g_evJoin, g_side);
        cudaStreamWaitEvent(0, g_evJoin, 0);
    }

    if (g_res_ok == 1) {
        // chunked: gemm2(chunk0) on side stream overlaps agg1(chunk1) on main
        k_agg1 <<<(NSPLIT * 32 + 255) / 256, 256>>>(0, NSPLIT);
        cudaEventRecord(g_evA, 0);
        k_agg1 <<<((NN - NSPLIT) * 32 + 255) / 256, 256>>>(NSPLIT, NN);
        cudaStreamWaitEvent(g_side, g_evA, 0);
        k_gemm2 <<<NSPLIT / 128, 128, 0, g_side>>>(W2, a2s, a2d, 0);
        cudaEventRecord(g_evB, g_side);
        k_gemm2 <<<(NN - NSPLIT + 127) / 128, 128>>>(W2, a2s, a2d, NSPLIT);
        cudaStreamWaitEvent(0, g_evB, 0);
    } else {
        k_agg1 <<<(NN * 32 + 255) / 256, 256>>>(0, NN);
        k_gemm2 <<<(NN + 127) / 128, 128>>>(W2, a2s, a2d, 0);
    }

    k_agg2 <<<(NN * 32 + 255) / 256, 256>>>(out);
}

// round 17
// speedup vs baseline: 1.0959x; 1.0092x over previous
#include <cuda_runtime.h>
#include <cuda_bf16.h>
#include <cuda_fp16.h>
#include <cstdint>
#include <math.h>

#define NN 100000
#define NE 1600000
#define NE_HALF 800000
#define SCAN_B 98    // ceil(NN/1024)
#define NSPLIT 50048 // chunk boundary (multiple of 128)

// ---------------- scratch (static device memory; no allocations) ----------------
__device__ int    g_is64;
__device__ int    g_deg[NN];      // zero-init at load; re-zeroed at end of k_scatter
__device__ int    g_incl[NN];
__device__ int    g_bsum[SCAN_B];
__device__ int    g_off[NN + 1];
__device__ int    g_pos[NE];
__device__ int    g_srcs[NE];
__device__ __half g_h1[NN * 64];     // layer-1 features, fp16 (values only)
__device__ float  g_s1[NN * 8];
__device__ float  g_t1[NN * 8];
__device__ float  g_z [NN * 64];
__device__ __half g_h2[NN * 16];     // layer-2 features, fp16 (values only)
__device__ float  g_s2[NN];
__device__ float  g_t2[NN];
__device__ __nv_bfloat16 g_w1h[256 * 64];   // W1 split, [n][k] n-major
__device__ __nv_bfloat16 g_w1l[256 * 64];

// ---------------- init: detect edge dtype only (1 warp; g_deg zeroed by scatter) ----------------
__global__ void k_init(const int* __restrict__ w) {
    if (threadIdx.x == 0) {
        int is64 = 1;
        #pragma unroll
        for (int k = 0; k < 8; k++)
            if (w[2 * k + 1] != 0) is64 = 0;
        g_is64 = is64;
    }
}

// histogram over a range of edges + record each edge's slot (single atomic pass).
// Safe to run ranges concurrently on two streams: atomics are device-wide; any
// permutation of slots per dst is a valid CSR ordering.
__global__ void k_hist(const int* __restrict__ w, int i0, int i1) {
    int i = i0 + blockIdx.x * blockDim.x + threadIdx.x;
    if (i >= i1) return;
    long long di = g_is64 ? 2LL * (NE + (long long)i) : (long long)(NE + i);
    g_pos[i] = atomicAdd(&g_deg[w[di]], 1);
}

__global__ void k_scanA() {
    __shared__ int sh[1024];
    int i = blockIdx.x * 1024 + threadIdx.x;
    int v = (i < NN) ? g_deg[i] : 0;
    sh[threadIdx.x] = v;
    __syncthreads();
    #pragma unroll
    for (int ofs = 1; ofs < 1024; ofs <<= 1) {
        int add = (threadIdx.x >= ofs) ? sh[threadIdx.x - ofs] : 0;
        __syncthreads();
        sh[threadIdx.x] += add;
        __syncthreads();
    }
    if (i < NN) g_incl[i] = sh[threadIdx.x];
    if (threadIdx.x == 1023) g_bsum[blockIdx.x] = sh[1023];
}

// fused: every block redundantly scans the 98 block sums, then writes its g_off slice.
__global__ void k_scanC() {
    __shared__ int sh[256];
    __shared__ int boff_s[256];
    int t = threadIdx.x;
    int v = (t < SCAN_B) ? g_bsum[t] : 0;
    sh[t] = v;
    __syncthreads();
    #pragma unroll
    for (int ofs = 1; ofs < 256; ofs <<= 1) {
        int add = (t >= ofs) ? sh[t - ofs] : 0;
        __syncthreads();
        sh[t] += add;
        __syncthreads();
    }
    boff_s[t] = sh[t] - v;    // exclusive prefix of block sums
    __syncthreads();

    int i = blockIdx.x * 256 + t;
    if (i < NN) g_off[i + 1] = g_incl[i] + boff_s[i >> 10];
    if (i == 0) g_off[0] = 0;
}

// pure gather+store, no atomics (slot precomputed in k_hist).
// Re-zeroes g_deg (already consumed by scanA/scanC) for the next graph replay.
__global__ void k_scatter(const int* __restrict__ w) {
    int i = blockIdx.x * blockDim.x + threadIdx.x;
    if (i >= NE) return;
    int is64 = g_is64;
    int s = w[is64 ? 2LL * i : (long long)i];
    int d = w[is64 ? 2LL * (NE + (long long)i) : (long long)(NE + i)];
    g_srcs[g_off[d] + g_pos[i]] = s;
    if (i < NN) g_deg[i] = 0;
}

// ---------------- W1 bf16 hi/lo split (once per call, tiny) ----------------
__global__ void k_prepW(const float* __restrict__ W1) {
    int i = blockIdx.x * blockDim.x + threadIdx.x;
    if (i >= 256 * 64) return;
    int k = i >> 6, n = i & 63;
    float v = W1[i];
    __nv_bfloat16 h = __float2bfloat16(v);
    __nv_bfloat16 l = __float2bfloat16(v - __bfloat162float(h));
    g_w1h[n * 256 + k] = h;
    g_w1l[n * 256 + k] = l;
}

// ---------------- GEMM1 on HMMA: h1 = x @ W1, bf16 3-term split ----------------
#define MMA16816(d, a, b0r, b1r) \
    asm volatile("mma.sync.aligned.m16n8k16.row.col.f32.bf16.bf16.f32 " \
        "{%0,%1,%2,%3}, {%4,%5,%6,%7}, {%8,%9}, {%0,%1,%2,%3};" \
        : "+f"((d)[0]), "+f"((d)[1]), "+f"((d)[2]), "+f"((d)[3]) \
        : "r"((a)[0]), "r"((a)[1]), "r"((a)[2]), "r"((a)[3]), "r"(b0r), "r"(b1r))

__global__ __launch_bounds__(128) void k_gemm1(
    const float* __restrict__ x,
    const float* __restrict__ a1s, const float* __restrict__ a1d)
{
    // stride 20 u32 -> frag LDS banks (20*(l>>2)+c)&31 all distinct: conflict-free
    __shared__ uint32_t xh[128][20], xl[128][20], wh[64][20], wl[64][20];
    const int t = threadIdx.x;
    const int w = t >> 5, l = t & 31;
    const int gid = l >> 2;   // groupID (row/col within fragment)
    const int c   = l & 3;    // thread-in-group (k pair / col pair)
    const int rowblk = blockIdx.x * 128;

    float acc[2][8][4];
    #pragma unroll
    for (int mt = 0; mt < 2; mt++)
        #pragma unroll
        for (int nt = 0; nt < 8; nt++)
            #pragma unroll
            for (int q = 0; q < 4; q++) acc[mt][nt][q] = 0.f;

    const uint32_t* wph = (const uint32_t*)g_w1h;
    const uint32_t* wpl = (const uint32_t*)g_w1l;

    for (int kc = 0; kc < 8; kc++) {
        // stage x chunk: 128 rows x 32 cols fp32 -> bf16 hi/lo packed pairs
        #pragma unroll
        for (int it = 0; it < 8; it++) {
            int f = (it << 7) + t;
            int row = f >> 3, c4 = f & 7;
            int grow = rowblk + row;
            float4 v = make_float4(0.f, 0.f, 0.f, 0.f);
            if (grow < NN) v = *(const float4*)&x[grow * 256 + (kc << 5) + (c4 << 2)];
            uint32_t uh0, uh1, ul0, ul1;
            asm("cvt.rn.bf16x2.f32 %0, %1, %2;" : "=r"(uh0) : "f"(v.y), "f"(v.x));
            asm("cvt.rn.bf16x2.f32 %0, %1, %2;" : "=r"(uh1) : "f"(v.w), "f"(v.z));
            float e0 = v.x - __uint_as_float(uh0 << 16);
            float e1 = v.y - __uint_as_float(uh0 & 0xffff0000u);
            float e2 = v.z - __uint_as_float(uh1 << 16);
            float e3 = v.w - __uint_as_float(uh1 & 0xffff0000u);
            asm("cvt.rn.bf16x2.f32 %0, %1, %2;" : "=r"(ul0) : "f"(e1), "f"(e0));
            asm("cvt.rn.bf16x2.f32 %0, %1, %2;" : "=r"(ul1) : "f"(e3), "f"(e2));
            xh[row][(c4 << 1)]     = uh0;
            xh[row][(c4 << 1) + 1] = uh1;
            xl[row][(c4 << 1)]     = ul0;
            xl[row][(c4 << 1) + 1] = ul1;
        }
        // stage W chunk: [64 n][16 kpairs] = 1024 entries -> 8 iterations of 128 threads
        #pragma unroll
        for (int it = 0; it < 8; it++) {
            int f = (it << 7) + t;
            int n = f >> 4, idx = f & 15;
            wh[n][idx] = wph[n * 128 + (kc << 4) + idx];
            wl[n][idx] = wpl[n * 128 + (kc << 4) + idx];
        }
        __syncthreads();

        #pragma unroll
        for (int ks = 0; ks < 2; ks++) {
            int kb = ks << 3;
            int r0 = (w << 5) + gid;
            uint32_t ah0[4] = { xh[r0][kb+c],    xh[r0+8][kb+c],    xh[r0][kb+c+4],    xh[r0+8][kb+c+4] };
            uint32_t ah1[4] = { xh[r0+16][kb+c], xh[r0+24][kb+c],   xh[r0+16][kb+c+4], xh[r0+24][kb+c+4] };
            uint32_t al0[4] = { xl[r0][kb+c],    xl[r0+8][kb+c],    xl[r0][kb+c+4],    xl[r0+8][kb+c+4] };
            uint32_t al1[4] = { xl[r0+16][kb+c], xl[r0+24][kb+c],   xl[r0+16][kb+c+4], xl[r0+24][kb+c+4] };
            #pragma unroll
            for (int nt = 0; nt < 8; nt++) {
                int n = (nt << 3) + gid;
                uint32_t bh0 = wh[n][kb+c], bh1 = wh[n][kb+c+4];
                uint32_t bl0 = wl[n][kb+c], bl1 = wl[n][kb+c+4];
                MMA16816(acc[0][nt], ah0, bh0, bh1);
                MMA16816(acc[1][nt], ah1, bh0, bh1);
                MMA16816(acc[0][nt], ah0, bl0, bl1);
                MMA16816(acc[1][nt], ah1, bl0, bl1);
                MMA16816(acc[0][nt], al0, bh0, bh1);
                MMA16816(acc[1][nt], al1, bh0, bh1);
            }
        }
        __syncthreads();
    }

    // ---- epilogue: store h1 (fp16) + s1/t1 (fp32) ----
    float as0[8], as1[8], ad0[8], ad1[8];
    #pragma unroll
    for (int nt = 0; nt < 8; nt++) {
        as0[nt] = __ldg(&a1s[(nt << 3) + (c << 1)]);
        as1[nt] = __ldg(&a1s[(nt << 3) + (c << 1) + 1]);
        ad0[nt] = __ldg(&a1d[(nt << 3) + (c << 1)]);
        ad1[nt] = __ldg(&a1d[(nt << 3) + (c << 1) + 1]);
    }
    #pragma unroll
    for (int mt = 0; mt < 2; mt++) {
        #pragma unroll
        for (int hf = 0; hf < 2; hf++) {
            int r = rowblk + (w << 5) + (mt << 4) + (hf << 3) + gid;
            bool ok = (r < NN);
            #pragma unroll
            for (int nt = 0; nt < 8; nt++) {
                float d0 = acc[mt][nt][(hf << 1)];
                float d1 = acc[mt][nt][(hf << 1) + 1];
                if (ok) {
                    uint32_t hp;   // lo = d0 (ch), hi = d1 (ch+1)
                    asm("cvt.rn.f16x2.f32 %0, %1, %2;" : "=r"(hp) : "f"(d1), "f"(d0));
                    *(uint32_t*)&g_h1[r * 64 + (nt << 3) + (c << 1)] = hp;
                }
                float sp = d0 * as0[nt] + d1 * as1[nt];
                float tp = d0 * ad0[nt] + d1 * ad1[nt];
                sp += __shfl_xor_sync(0xffffffffu, sp, 1);
                sp += __shfl_xor_sync(0xffffffffu, sp, 2);
                tp += __shfl_xor_sync(0xffffffffu, tp, 1);
                tp += __shfl_xor_sync(0xffffffffu, tp, 2);
                if (ok && c == 0) { g_s1[r * 8 + nt] = sp; g_t1[r * 8 + nt] = tp; }
            }
        }
    }
}

// ---------------- Layer-1 aggregation: warp per dst node, 4 edges per iteration ----------------
__global__ void k_agg1(int n0, int n1) {
    int n = n0 + ((blockIdx.x * blockDim.x + threadIdx.x) >> 5);
    if (n >= n1) return;
    const int lane = threadIdx.x & 31;
    const int grp  = lane >> 3;       // which edge of the quad
    const int h    = lane & 7;        // head 0..7 (channels 8h..8h+7)

    const float tn = g_t1[n * 8 + h];
    const int j0 = g_off[n], j1 = g_off[n + 1];

    float d = 0.f;
    float A0 = 0.f, A1 = 0.f, A2 = 0.f, A3 = 0.f;
    float A4 = 0.f, A5 = 0.f, A6 = 0.f, A7 = 0.f;

    #pragma unroll 2
    for (int j = j0 + grp; j < j1; j += 4) {
        int src = __ldg(&g_srcs[j]);
        float e = __ldg(&g_s1[src * 8 + h]) + tn;
        e = e > 0.f ? e : 0.2f * e;
        float p = __expf(e);
        uint4 hv = __ldg((const uint4*)&g_h1[src * 64 + (h << 3)]);
        float2 f0 = __half22float2(*(const __half2*)&hv.x);
        float2 f1 = __half22float2(*(const __half2*)&hv.y);
        float2 f2 = __half22float2(*(const __half2*)&hv.z);
        float2 f3 = __half22float2(*(const __half2*)&hv.w);
        d  += p;
        A0 += p * f0.x; A1 += p * f0.y;
        A2 += p * f1.x; A3 += p * f1.y;
        A4 += p * f2.x; A5 += p * f2.y;
        A6 += p * f3.x; A7 += p * f3.y;
    }
    #pragma unroll
    for (int o = 8; o <= 16; o <<= 1) {
        d  += __shfl_xor_sync(0xffffffffu, d,  o);
        A0 += __shfl_xor_sync(0xffffffffu, A0, o);
        A1 += __shfl_xor_sync(0xffffffffu, A1, o);
        A2 += __shfl_xor_sync(0xffffffffu, A2, o);
        A3 += __shfl_xor_sync(0xffffffffu, A3, o);
        A4 += __shfl_xor_sync(0xffffffffu, A4, o);
        A5 += __shfl_xor_sync(0xffffffffu, A5, o);
        A6 += __shfl_xor_sync(0xffffffffu, A6, o);
        A7 += __shfl_xor_sync(0xffffffffu, A7, o);
    }

    if (grp == 0) {
        float inv = 1.f / (d + 1e-16f);
        float r0 = A0 * inv, r1 = A1 * inv, r2 = A2 * inv, r3 = A3 * inv;
        float r4 = A4 * inv, r5 = A5 * inv, r6 = A6 * inv, r7 = A7 * inv;
        float4 za, zb;
        za.x = r0 > 0.f ? r0 : expm1f(r0);   // elu
        za.y = r1 > 0.f ? r1 : expm1f(r1);
        za.z = r2 > 0.f ? r2 : expm1f(r2);
        za.w = r3 > 0.f ? r3 : expm1f(r3);
        zb.x = r4 > 0.f ? r4 : expm1f(r4);
        zb.y = r5 > 0.f ? r5 : expm1f(r5);
        zb.z = r6 > 0.f ? r6 : expm1f(r6);
        zb.w = r7 > 0.f ? r7 : expm1f(r7);
        float4* zp = (float4*)&g_z[n * 64 + (h << 3)];
        zp[0] = za;
        zp[1] = zb;
    }
}

// ---------------- GEMM2: h2 = z @ W2 (+ s2/t2 epilogue), h2 stored fp16 ----------------
__global__ __launch_bounds__(128) void k_gemm2(
    const float* __restrict__ W2, const float* __restrict__ a2s, const float* __restrict__ a2d,
    int row0)
{
    __shared__ float zs[128][65];
    __shared__ __align__(16) float w2s[1024];
    const int t = threadIdx.x;
    const int base = row0 + blockIdx.x * 128;

    #pragma unroll
    for (int r = 0; r < 64; r++) {
        int i = (r << 7) + t;
        int row = i >> 6, col = i & 63;
        int grow = base + row;
        zs[row][col] = (grow < NN) ? g_z[grow * 64 + col] : 0.f;
    }
    #pragma unroll
    for (int r = 0; r < 8; r++) w2s[(r << 7) + t] = W2[(r << 7) + t];
    __syncthreads();

    int row = base + t;
    if (row >= NN) return;

    float acc[16];
    #pragma unroll
    for (int cc = 0; cc < 16; cc++) acc[cc] = 0.f;

    #pragma unroll 8
    for (int k = 0; k < 64; k++) {
        float a = zs[t][k];
        const float4* wp = (const float4*)&w2s[k << 4];
        float4 w0 = wp[0], w1 = wp[1], w2 = wp[2], w3 = wp[3];
        acc[0]  += a * w0.x; acc[1]  += a * w0.y; acc[2]  += a * w0.z; acc[3]  += a * w0.w;
        acc[4]  += a * w1.x; acc[5]  += a * w1.y; acc[6]  += a * w1.z; acc[7]  += a * w1.w;
        acc[8]  += a * w2.x; acc[9]  += a * w2.y; acc[10] += a * w2.z; acc[11] += a * w2.w;
        acc[12] += a * w3.x; acc[13] += a * w3.y; acc[14] += a * w3.z; acc[15] += a * w3.w;
    }

    float s = 0.f, tt = 0.f;
    #pragma unroll
    for (int cc = 0; cc < 16; cc++) { s += acc[cc] * a2s[cc]; tt += acc[cc] * a2d[cc]; }
    g_s2[row] = s;
    g_t2[row] = tt;

    uint32_t hp[8];
    #pragma unroll
    for (int cc = 0; cc < 8; cc++)
        asm("cvt.rn.f16x2.f32 %0, %1, %2;" : "=r"(hp[cc]) : "f"(acc[2*cc+1]), "f"(acc[2*cc]));
    uint4* op = (uint4*)&g_h2[row * 16];
    op[0] = make_uint4(hp[0], hp[1], hp[2], hp[3]);
    op[1] = make_uint4(hp[4], hp[5], hp[6], hp[7]);
}

// ---------------- Layer-2 aggregation + log_softmax fused, 4 edges per iteration ----------------
__global__ void k_agg2(float* __restrict__ out) {
    int n = (blockIdx.x * blockDim.x + threadIdx.x) >> 5;
    if (n >= NN) return;
    const int lane = threadIdx.x & 31;
    const int grp  = lane >> 3;
    const int g    = lane & 7;        // class pair (2g, 2g+1)

    const float tn = g_t2[n];
    const int j0 = g_off[n], j1 = g_off[n + 1];

    float d = 0.f, A0 = 0.f, A1 = 0.f;
    #pragma unroll 2
    for (int j = j0 + grp; j < j1; j += 4) {
        int src = __ldg(&g_srcs[j]);
        float e = __ldg(&g_s2[src]) + tn;
        e = e > 0.f ? e : 0.2f * e;
        float p = __expf(e);
        __half2 hv = __ldg((const __half2*)&g_h2[src * 16 + (g << 1)]);
        float2 f = __half22float2(hv);
        d  += p;
        A0 += p * f.x;
        A1 += p * f.y;
    }
    #pragma unroll
    for (int o = 8; o <= 16; o <<= 1) {
        d  += __shfl_xor_sync(0xffffffffu, d,  o);
        A0 += __shfl_xor_sync(0xffffffffu, A0, o);
        A1 += __shfl_xor_sync(0xffffffffu, A1, o);
    }

    float inv = 1.f / (d + 1e-16f);
    float l0 = A0 * inv, l1 = A1 * inv;

    float mx = fmaxf(l0, l1);
    #pragma unroll
    for (int o = 1; o <= 4; o <<= 1) mx = fmaxf(mx, __shfl_xor_sync(0xffffffffu, mx, o));
    float sm = expf(l0 - mx) + expf(l1 - mx);
    #pragma unroll
    for (int o = 1; o <= 4; o <<= 1) sm += __shfl_xor_sync(0xffffffffu, sm, o);
    float lg = logf(sm);
    if (grp == 0)
        *(float2*)&out[n * 16 + (g << 1)] = make_float2(l0 - mx - lg, l1 - mx - lg);
}

// ---------------- launch: hist split across streams; scatter hidden under gemm1 ----------------
static cudaStream_t g_side = 0;
static cudaEvent_t  g_evFork = 0, g_evJoin = 0, g_evA = 0, g_evB = 0, g_evH = 0;
static int g_res_ok = -1;

extern "C" void kernel_launch(void* const* d_in, const int* in_sizes, int n_in,
                              void* d_out, int out_size) {
    const float* x   = (const float*)d_in[0];
    const int*   ei  = (const int*)  d_in[1];
    const float* W1  = (const float*)d_in[2];
    const float* a1s = (const float*)d_in[3];
    const float* a1d = (const float*)d_in[4];
    const float* W2  = (const float*)d_in[5];
    const float* a2s = (const float*)d_in[6];
    const float* a2d = (const float*)d_in[7];
    float* out = (float*)d_out;

    if (g_res_ok < 0) {   // one-time resource creation (first call is uncaptured)
        cudaError_t e1 = cudaStreamCreateWithFlags(&g_side, cudaStreamNonBlocking);
        cudaError_t e2 = cudaEventCreateWithFlags(&g_evFork, cudaEventDisableTiming);
        cudaError_t e3 = cudaEventCreateWithFlags(&g_evJoin, cudaEventDisableTiming);
        cudaError_t e4 = cudaEventCreateWithFlags(&g_evA, cudaEventDisableTiming);
        cudaError_t e5 = cudaEventCreateWithFlags(&g_evB, cudaEventDisableTiming);
        cudaError_t e6 = cudaEventCreateWithFlags(&g_evH, cudaEventDisableTiming);
        g_res_ok = (e1 == cudaSuccess && e2 == cudaSuccess && e3 == cudaSuccess &&
                    e4 == cudaSuccess && e5 == cudaSuccess && e6 == cudaSuccess) ? 1 : 0;
    }

    if (g_res_ok == 1) {
        // init (detect dtype) on main, then fork
        k_init <<<1, 32>>>(ei);
        cudaEventRecord(g_evFork, 0);
        cudaStreamWaitEvent(g_side, g_evFork, 0);

        // both streams histogram half the edges concurrently
        k_hist <<<(NE_HALF + 255) / 256, 256>>>(ei, 0, NE_HALF);           // main
        cudaEventRecord(g_evH, 0);
        k_hist <<<(NE_HALF + 255) / 256, 256, 0, g_side>>>(ei, NE_HALF, NE);

        // main proceeds to W split + GEMM1 (independent of CSR)
        k_prepW <<<(256 * 64 + 255) / 256, 256>>>(W1);
        k_gemm1 <<<(NN + 127) / 128, 128>>>(x, a1s, a1d);

        // side: wait for main's hist half, then scan + scatter (hidden under gemm1)
        cudaStreamWaitEvent(g_side, g_evH, 0);
        k_scanA   <<<SCAN_B, 1024, 0, g_side>>>();
        k_scanC   <<<(NN + 255) / 256, 256, 0, g_side>>>();
        k_scatter <<<(NE + 255) / 256, 256, 0, g_side>>>(ei);
        cudaEventRecord(g_evJoin, g_side);
        cudaStreamWaitEvent(0, g_evJoin, 0);

        // chunked: gemm2(chunk0) on side stream overlaps agg1(chunk1) on main
        k_agg1 <<<(NSPLIT * 32 + 255) / 256, 256>>>(0, NSPLIT);
        cudaEventRecord(g_evA, 0);
        k_agg1 <<<((NN - NSPLIT) * 32 + 255) / 256, 256>>>(NSPLIT, NN);
        cudaStreamWaitEvent(g_side, g_evA, 0);
        k_gemm2 <<<NSPLIT / 128, 128, 0, g_side>>>(W2, a2s, a2d, 0);
        cudaEventRecord(g_evB, g_side);
        k_gemm2 <<<(NN - NSPLIT + 127) / 128, 128>>>(W2, a2s, a2d, NSPLIT);
        cudaStreamWaitEvent(0, g_evB, 0);
    } else {
        // serial fallback
        k_init    <<<1, 32>>>(ei);
        k_hist    <<<(NE_HALF + 255) / 256, 256>>>(ei, 0, NE_HALF);
        k_hist    <<<(NE_HALF + 255) / 256, 256>>>(ei, NE_HALF, NE);
        k_scanA   <<<SCAN_B, 1024>>>();
        k_scanC   <<<(NN + 255) / 256, 256>>>();
        k_scatter <<<(NE + 255) / 256, 256>>>(ei);
        k_prepW   <<<(256 * 64 + 255) / 256, 256>>>(W1);
        k_gemm1   <<<(NN + 127) / 128, 128>>>(x, a1s, a1d);
        k_agg1    <<<(NN * 32 + 255) / 256, 256>>>(0, NN);
        k_gemm2   <<<(NN + 127) / 128, 128>>>(W2, a2s, a2d, 0);
    }

    k_agg2 <<<(NN * 32 + 255) / 256, 256>>>(out);
}